// round 14
// baseline (speedup 1.0000x reference)
#include <cuda_runtime.h>
#include <cuda_fp16.h>
#include <math.h>
#include <stdint.h>

// Problem constants: B=4, L=2048 -> N=8192 tokens
#define NTOK 8192
#define DDIM 1024
#define HDIM 2048
#define NEXP 8
#define NSH 2
#define MAXP (2 * NTOK)
#define MAXP_PAD (MAXP + NEXP * 128)  // 17408
#define TILES_MAX (MAXP_PAD / 128)    // 136
#define MT_S (NTOK / 128)             // 64

// GEMM staging geometry (words = 32-bit packed fp16 pairs)
// CTA tile 128x128, BK=32 (16 kpairs). A hi/lo + B hi: 128 rows x 16 words, stride 20.
#define NSTG 4
#define RSTRIDE 20
#define AH_OFF 0
#define AL_OFF 2560                    // 128*20
#define BH_OFF 5120
#define STG_W 7680                     // words per stage (30KB)
#define SMEMSZ (NSTG * STG_W * 4)      // 122880 bytes

// ------------------------- scratch (__device__ globals) -------------------------
__device__ unsigned g_x_hi [(size_t)NTOK * 512];
__device__ unsigned g_x_lo [(size_t)NTOK * 512];
__device__ unsigned g_xg_hi[(size_t)MAXP_PAD * 512];
__device__ unsigned g_xg_lo[(size_t)MAXP_PAD * 512];
__device__ unsigned g_h_hi [(size_t)MAXP_PAD * 1024];
__device__ unsigned g_h_lo [(size_t)MAXP_PAD * 1024];
__device__ unsigned g_hs_hi[(size_t)NSH * NTOK * 1024];
__device__ unsigned g_hs_lo[(size_t)NSH * NTOK * 1024];
__device__ unsigned g_w1t_hi[(size_t)NEXP * 512 * HDIM];
__device__ unsigned g_w2t_hi[(size_t)NEXP * 1024 * DDIM];
__device__ unsigned g_s1t_hi[(size_t)NSH * 512 * HDIM];
__device__ unsigned g_s2t_hi[(size_t)NSH * 1024 * DDIM];
__device__ float g_ybuf[(size_t)MAXP_PAD * DDIM];
__device__ float g_ys[(size_t)NSH * NTOK * DDIM];
__device__ int   g_pair_token[MAXP_PAD];
__device__ int   g_slot_of[MAXP];
__device__ float g_gate[MAXP];
__device__ int   g_topi[MAXP];
__device__ int   g_tile_expert[TILES_MAX];

// ------------------------- helpers -------------------------
__device__ __forceinline__ uint32_t smem_u32(const void* p) {
    uint32_t a;
    asm("{ .reg .u64 t; cvta.to.shared.u64 t, %1; cvt.u32.u64 %0, t; }" : "=r"(a) : "l"(p));
    return a;
}
__device__ __forceinline__ void cp16(uint32_t dst, const void* src) {
    asm volatile("cp.async.cg.shared.global [%0], [%1], 16;" :: "r"(dst), "l"(src) : "memory");
}
#define CP_COMMIT() asm volatile("cp.async.commit_group;" ::: "memory")
#define CP_WAIT2() asm volatile("cp.async.wait_group 2;" ::: "memory")

#define LDSM4(r0, r1, r2, r3, addr)                                           \
    asm volatile("ldmatrix.sync.aligned.m8n8.x4.shared.b16 {%0,%1,%2,%3},[%4];" \
                 : "=r"(r0), "=r"(r1), "=r"(r2), "=r"(r3) : "r"(addr))
#define LDSM2(r0, r1, addr)                                                   \
    asm volatile("ldmatrix.sync.aligned.m8n8.x2.shared.b16 {%0,%1},[%2];"     \
                 : "=r"(r0), "=r"(r1) : "r"(addr))

// fp16 split: x = hi + lo; hi captures ~12 bits, lo the next ~12 (A operand)
__device__ __forceinline__ void cvt_pair_h(float x0, float x1, unsigned& hi, unsigned& lo) {
    __half h0 = __float2half_rn(x0);
    __half h1 = __float2half_rn(x1);
    float r0 = x0 - __half2float(h0);
    float r1 = x1 - __half2float(h1);
    __half l0 = __float2half_rn(r0);
    __half l1 = __float2half_rn(r1);
    hi = (unsigned)__half_as_ushort(h0) | ((unsigned)__half_as_ushort(h1) << 16);
    lo = (unsigned)__half_as_ushort(l0) | ((unsigned)__half_as_ushort(l1) << 16);
}
// fp16 single (B operand)
__device__ __forceinline__ unsigned cvt_one_h(float x0, float x1) {
    return (unsigned)__half_as_ushort(__float2half_rn(x0)) |
           ((unsigned)__half_as_ushort(__float2half_rn(x1)) << 16);
}

#define MMA_F16(accp, a, b)                                                   \
    asm volatile(                                                             \
        "mma.sync.aligned.m16n8k16.row.col.f32.f16.f16.f32 "                  \
        "{%0,%1,%2,%3},{%4,%5,%6,%7},{%8,%9},{%0,%1,%2,%3};"                  \
        : "+f"((accp)[0]), "+f"((accp)[1]), "+f"((accp)[2]), "+f"((accp)[3])  \
        : "r"((a)[0]), "r"((a)[1]), "r"((a)[2]), "r"((a)[3]),                 \
          "r"((b)[0]), "r"((b)[1]))

// ------------------------- router -------------------------
__global__ void router_kernel(const float* __restrict__ x, const float* __restrict__ rw,
                              const float* __restrict__ rb, int N) {
    int w = (blockIdx.x * blockDim.x + threadIdx.x) >> 5;
    int lane = threadIdx.x & 31;
    if (w >= N) return;
    const float* xr = x + (size_t)w * DDIM;
    float acc[NEXP];
#pragma unroll
    for (int e = 0; e < NEXP; e++) acc[e] = 0.f;
    for (int d = lane; d < DDIM; d += 32) {
        float xv = xr[d];
        const float* r = rw + (size_t)d * NEXP;
#pragma unroll
        for (int e = 0; e < NEXP; e++) acc[e] = fmaf(xv, r[e], acc[e]);
    }
#pragma unroll
    for (int e = 0; e < NEXP; e++)
        for (int o = 16; o > 0; o >>= 1) acc[e] += __shfl_xor_sync(0xffffffffu, acc[e], o);
    if (lane == 0) {
        float v0 = -1e30f, v1 = -1e30f;
        int i0 = 0, i1 = 0;
#pragma unroll
        for (int e = 0; e < NEXP; e++) {
            float v = acc[e] + rb[e];
            if (v > v0) { v1 = v0; i1 = i0; v0 = v; i0 = e; }
            else if (v > v1) { v1 = v; i1 = e; }
        }
        float p1 = expf(v1 - v0);
        float inv = 1.0f / (1.0f + p1);
        g_topi[2 * w] = i0; g_topi[2 * w + 1] = i1;
        g_gate[2 * w] = inv; g_gate[2 * w + 1] = p1 * inv;
    }
}

// ------------------------- bucketing -------------------------
__global__ void bucket_kernel(int N) {
    __shared__ int s_cnt[NEXP];
    __shared__ int s_off[NEXP + 1];
    __shared__ int s_c2[NEXP];
    int tid = threadIdx.x;
    if (tid < NEXP) { s_cnt[tid] = 0; s_c2[tid] = 0; }
    __syncthreads();
    int P = 2 * N;
    for (int p = tid; p < P; p += blockDim.x) atomicAdd(&s_cnt[g_topi[p]], 1);
    for (int i = tid; i < MAXP_PAD; i += blockDim.x) g_pair_token[i] = -1;
    __syncthreads();
    if (tid == 0) {
        int o = 0;
        for (int e = 0; e < NEXP; e++) { s_off[e] = o; o += ((s_cnt[e] + 127) >> 7) << 7; }
        s_off[NEXP] = o;
        int total = o >> 7;
        for (int t = 0; t < TILES_MAX; t++) {
            int ex = -1;
            if (t < total) {
                int s = t << 7;
                for (int e = 0; e < NEXP; e++)
                    if (s >= s_off[e] && s < s_off[e + 1]) ex = e;
            }
            g_tile_expert[t] = ex;
        }
    }
    __syncthreads();
    for (int p = tid; p < P; p += blockDim.x) {
        int e = g_topi[p];
        int pos = atomicAdd(&s_c2[e], 1);
        int slot = s_off[e] + pos;
        g_pair_token[slot] = p >> 1;
        g_slot_of[p] = slot;
    }
}

// ------------------------- operand pre-conversion -------------------------
// x (fp32 row-major) -> packed fp16 hi/lo words, row-major [n][D/2]
__global__ void pack_x_kernel(const float* __restrict__ x) {
    size_t idx = (size_t)blockIdx.x * blockDim.x + threadIdx.x;
    if (idx >= (size_t)NTOK * 512) return;
    float2 v = *(const float2*)(x + 2 * idx);
    unsigned h, l; cvt_pair_h(v.x, v.y, h, l);
    g_x_hi[idx] = h; g_x_lo[idx] = l;
}
// gathered x by slot -> [slot][D/2]
__global__ void pack_xg_kernel(const float* __restrict__ x) {
    size_t idx = (size_t)blockIdx.x * blockDim.x + threadIdx.x;
    if (idx >= (size_t)MAXP_PAD * 512) return;
    int slot = (int)(idx >> 9), w = (int)(idx & 511);
    int tok = g_pair_token[slot];
    float2 v = (tok >= 0) ? *(const float2*)(x + (size_t)tok * DDIM + 2 * w)
                          : make_float2(0.f, 0.f);
    unsigned h, l; cvt_pair_h(v.x, v.y, h, l);
    g_xg_hi[idx] = h; g_xg_lo[idx] = l;
}
// W [Z][K][N] fp32 -> n-major blocks [(z*NT+nt)*KC + kc][n 128][kpair 16], single fp16
__global__ void wt_kernel(const float* __restrict__ W,
                          unsigned* __restrict__ oh,
                          int K, int N) {
    __shared__ float t[64][33];
    int z = blockIdx.z;
    const float* Wz = W + (size_t)z * K * N;
    int k0 = blockIdx.y * 64, n0 = blockIdx.x * 32;
    int tx = threadIdx.x, ty = threadIdx.y;
#pragma unroll
    for (int i = 0; i < 8; i++) {
        int k = ty + i * 8;
        t[k][tx] = Wz[(size_t)(k0 + k) * N + n0 + tx];
    }
    __syncthreads();
    int tid = ty * 32 + tx;
    int nl = tid >> 3, w8 = tid & 7;
    int NT = N >> 7, KC = K >> 5;
    int nabs = n0 + nl, nt = nabs >> 7, nin = nabs & 127;
#pragma unroll
    for (int kcb = 0; kcb < 2; kcb++) {
        int kc = (k0 >> 5) + kcb;
        size_t base = ((size_t)(z * NT + nt) * KC + kc) * 2048 + (size_t)nin * 16;
#pragma unroll
        for (int j = 0; j < 2; j++) {
            int kp = w8 * 2 + j;
            int kloc = kcb * 32 + kp * 2;
            oh[base + kp] = cvt_one_h(t[kloc][nl], t[kloc + 1][nl]);
        }
    }
}

// ------------------------- mma.sync GEMM: 128x128 tile, 512 threads, 32x32/warp -------------------------
// 16 warps (4M x 4N), BK=32 (16 kpairs), fp16x2 on A (hi+lo) x single-fp16 B:
// (Ah+Al)@Bh = A@Bh; error = A@(B-Bh) ~ 2^-12 relative. 2 MMA passes per fragment.
// 4-stage cp.async pipeline, ldmatrix fragment loads.
// GELU=0: C fp32 += bias. GELU=1: gelu(C+bias) -> packed fp16 hi/lo words (A-format).
template <int GELU>
__global__ void __launch_bounds__(512, 1)
mma_gemm2(const unsigned* __restrict__ Ah, const unsigned* __restrict__ Al,
          long long a_z, int a_ld,
          const unsigned* __restrict__ Bh,
          const float* __restrict__ bias_base, int bias_stride,
          float* __restrict__ Cf, long long c_z, int c_ld,
          unsigned* __restrict__ Oh, unsigned* __restrict__ Ol,
          long long o_z, int o_ld,
          const int* __restrict__ te, int nKb, int NTtot) {
    int nt = blockIdx.x, mt = blockIdx.y, z = blockIdx.z;
    int expert = te ? te[mt] : z;
    if (expert < 0) return;

    extern __shared__ unsigned smw[];
    uint32_t sb = smem_u32(smw);
    int tid = threadIdx.x, lane = tid & 31, wid = tid >> 5;
    int wm = (wid & 3) * 32, wn = (wid >> 2) * 32;
    int mBase = mt * 128;

    const unsigned* Abase_h = Ah + (size_t)z * a_z + (size_t)mBase * a_ld;
    const unsigned* Abase_l = Al + (size_t)z * a_z + (size_t)mBase * a_ld;
    const unsigned* Bbase_h = Bh + (size_t)(expert * NTtot + nt) * nKb * 2048;

    // copy decode: each array is 128 rows x 16 words = 512 x 16B chunks; 1 chunk/thread/array
    int rowC = tid >> 2, c4 = (tid & 3) * 4;

    auto issue = [&](int kb) {
        uint32_t st = sb + (uint32_t)((kb & (NSTG - 1)) * STG_W) * 4;
        cp16(st + (AH_OFF + rowC * RSTRIDE + c4) * 4,
             Abase_h + (size_t)rowC * a_ld + kb * 16 + c4);
        cp16(st + (AL_OFF + rowC * RSTRIDE + c4) * 4,
             Abase_l + (size_t)rowC * a_ld + kb * 16 + c4);
        cp16(st + (BH_OFF + rowC * RSTRIDE + c4) * 4,
             Bbase_h + (size_t)kb * 2048 + rowC * 16 + c4);
    };

    float acc[2][4][4];
#pragma unroll
    for (int a = 0; a < 2; a++)
#pragma unroll
        for (int b = 0; b < 4; b++)
#pragma unroll
            for (int c = 0; c < 4; c++) acc[a][b][c] = 0.f;

    // prologue: 3 stages in flight
#pragma unroll
    for (int s = 0; s < NSTG - 1; s++) {
        if (s < nKb) issue(s);
        CP_COMMIT();
    }

    // ldmatrix per-thread base offsets (bytes)
    uint32_t a_off = (uint32_t)((wm + (lane & 15)) * RSTRIDE + (lane >> 4) * 4) * 4;
    uint32_t b_off = (uint32_t)((wn + (lane & 7)) * RSTRIDE + ((lane >> 3) & 1) * 4) * 4;

    for (int kb = 0; kb < nKb; kb++) {
        CP_WAIT2();
        __syncthreads();
        int nx = kb + NSTG - 1;
        if (nx < nKb) issue(nx);
        CP_COMMIT();

        uint32_t stg = sb + (uint32_t)((kb & (NSTG - 1)) * STG_W) * 4;
        uint32_t aH = stg + AH_OFF * 4 + a_off;
        uint32_t aL = stg + AL_OFF * 4 + a_off;
        uint32_t bH = stg + BH_OFF * 4 + b_off;
#pragma unroll
        for (int ks = 0; ks < 2; ks++) {
            unsigned ah[2][4], al[2][4];
#pragma unroll
            for (int m2 = 0; m2 < 2; m2++) {
                uint32_t o = m2 * (16 * RSTRIDE * 4) + ks * 32;
                LDSM4(ah[m2][0], ah[m2][1], ah[m2][2], ah[m2][3], aH + o);
                LDSM4(al[m2][0], al[m2][1], al[m2][2], al[m2][3], aL + o);
            }
#pragma unroll
            for (int n8 = 0; n8 < 4; n8++) {
                unsigned bh[2];
                uint32_t o = n8 * (8 * RSTRIDE * 4) + ks * 32;
                LDSM2(bh[0], bh[1], bH + o);
#pragma unroll
                for (int m2 = 0; m2 < 2; m2++) MMA_F16(acc[m2][n8], ah[m2], bh);
#pragma unroll
                for (int m2 = 0; m2 < 2; m2++) MMA_F16(acc[m2][n8], al[m2], bh);
            }
        }
    }

    // epilogue
    const float* bias = bias_base + (size_t)expert * bias_stride + nt * 128;
#pragma unroll
    for (int m2 = 0; m2 < 2; m2++) {
#pragma unroll
        for (int n8 = 0; n8 < 4; n8++) {
            int row0 = mBase + wm + m2 * 16 + (lane >> 2);
            int c0 = wn + n8 * 8 + (lane & 3) * 2;
            float b0 = bias[c0], b1 = bias[c0 + 1];
            float v0 = acc[m2][n8][0] + b0;
            float v1 = acc[m2][n8][1] + b1;
            float v2 = acc[m2][n8][2] + b0;
            float v3 = acc[m2][n8][3] + b1;
            if (GELU) {
                v0 = 0.5f * v0 * (1.0f + erff(v0 * 0.70710678118654752f));
                v1 = 0.5f * v1 * (1.0f + erff(v1 * 0.70710678118654752f));
                v2 = 0.5f * v2 * (1.0f + erff(v2 * 0.70710678118654752f));
                v3 = 0.5f * v3 * (1.0f + erff(v3 * 0.70710678118654752f));
                unsigned h0, l0, h1, l1;
                cvt_pair_h(v0, v1, h0, l0);
                cvt_pair_h(v2, v3, h1, l1);
                size_t w = (size_t)((nt * 128 + c0) >> 1);
                size_t b0i = (size_t)z * o_z + (size_t)row0 * o_ld + w;
                size_t b1i = b0i + (size_t)8 * o_ld;
                Oh[b0i] = h0; Ol[b0i] = l0;
                Oh[b1i] = h1; Ol[b1i] = l1;
            } else {
                size_t base = (size_t)z * c_z + (size_t)row0 * c_ld + nt * 128 + c0;
                *(float2*)&Cf[base] = make_float2(v0, v1);
                *(float2*)&Cf[base + (size_t)8 * c_ld] = make_float2(v2, v3);
            }
        }
    }
}

// ------------------------- final combine -------------------------
__global__ void combine_kernel(float* __restrict__ out, int N) {
    int idx = blockIdx.x * blockDim.x + threadIdx.x;
    int total = N * (DDIM / 4);
    if (idx >= total) return;
    int n = idx / (DDIM / 4);
    int d = (idx % (DDIM / 4)) * 4;
    const float4 s0 = *(const float4*)&g_ys[(size_t)n * DDIM + d];
    const float4 s1 = *(const float4*)&g_ys[(size_t)N * DDIM + (size_t)n * DDIM + d];
    int sl0 = g_slot_of[2 * n], sl1 = g_slot_of[2 * n + 1];
    float w0 = g_gate[2 * n], w1 = g_gate[2 * n + 1];
    const float4 y0 = *(const float4*)&g_ybuf[(size_t)sl0 * DDIM + d];
    const float4 y1 = *(const float4*)&g_ybuf[(size_t)sl1 * DDIM + d];
    const float inv_s = 1.0f / NSH;
    float4 o;
    o.x = inv_s * (s0.x + s1.x) + w0 * y0.x + w1 * y1.x;
    o.y = inv_s * (s0.y + s1.y) + w0 * y0.y + w1 * y1.y;
    o.z = inv_s * (s0.z + s1.z) + w0 * y0.z + w1 * y1.z;
    o.w = inv_s * (s0.w + s1.w) + w0 * y0.w + w1 * y1.w;
    *(float4*)&out[(size_t)n * DDIM + d] = o;
}

// ------------------------- launch -------------------------
#define SYM(p, s) void* p; cudaGetSymbolAddress(&p, s)

extern "C" void kernel_launch(void* const* d_in, const int* in_sizes, int n_in,
                              void* d_out, int out_size) {
    const float* x   = (const float*)d_in[0];
    const float* rw  = (const float*)d_in[1];
    const float* rb  = (const float*)d_in[2];
    const float* w1  = (const float*)d_in[3];
    const float* b1  = (const float*)d_in[4];
    const float* w2  = (const float*)d_in[5];
    const float* b2  = (const float*)d_in[6];
    const float* sw1 = (const float*)d_in[7];
    const float* sb1 = (const float*)d_in[8];
    const float* sw2 = (const float*)d_in[9];
    const float* sb2 = (const float*)d_in[10];
    float* out = (float*)d_out;
    int N = in_sizes[0] / DDIM;

    cudaFuncSetAttribute(mma_gemm2<0>, cudaFuncAttributeMaxDynamicSharedMemorySize, SMEMSZ);
    cudaFuncSetAttribute(mma_gemm2<1>, cudaFuncAttributeMaxDynamicSharedMemorySize, SMEMSZ);

    SYM(p_xh, g_x_hi);    SYM(p_xl, g_x_lo);
    SYM(p_gh, g_xg_hi);   SYM(p_gl, g_xg_lo);
    SYM(p_hh, g_h_hi);    SYM(p_hl, g_h_lo);
    SYM(p_sh, g_hs_hi);   SYM(p_sl, g_hs_lo);
    SYM(p_w1h, g_w1t_hi);
    SYM(p_w2h, g_w2t_hi);
    SYM(p_s1h, g_s1t_hi);
    SYM(p_s2h, g_s2t_hi);
    SYM(p_yb, g_ybuf);    SYM(p_ys, g_ys);
    SYM(p_te, g_tile_expert);

    // 1) router + bucketing
    router_kernel<<<(N + 7) / 8, 256>>>(x, rw, rb, N);
    bucket_kernel<<<1, 256>>>(N);
    // 2) operand pre-conversion
    pack_x_kernel<<<(NTOK * 512 + 255) / 256, 256>>>(x);
    pack_xg_kernel<<<(MAXP_PAD * 512 + 255) / 256, 256>>>(x);
    dim3 tb(32, 8);
    wt_kernel<<<dim3(HDIM / 32, DDIM / 64, NEXP), tb>>>(w1, (unsigned*)p_w1h, DDIM, HDIM);
    wt_kernel<<<dim3(DDIM / 32, HDIM / 64, NEXP), tb>>>(w2, (unsigned*)p_w2h, HDIM, DDIM);
    wt_kernel<<<dim3(HDIM / 32, DDIM / 64, NSH), tb>>>(sw1, (unsigned*)p_s1h, DDIM, HDIM);
    wt_kernel<<<dim3(DDIM / 32, HDIM / 64, NSH), tb>>>(sw2, (unsigned*)p_s2h, HDIM, DDIM);
    // 3) routed GEMM1: h = gelu(xg @ w1[e] + b1[e]) -> packed fp16 hi/lo (A-format)
    mma_gemm2<1><<<dim3(HDIM / 128, TILES_MAX, 1), 512, SMEMSZ>>>(
        (unsigned*)p_gh, (unsigned*)p_gl, 0, 512,
        (unsigned*)p_w1h, b1, HDIM,
        nullptr, 0, 0, (unsigned*)p_hh, (unsigned*)p_hl, 0, 1024,
        (const int*)p_te, DDIM / 32, HDIM / 128);
    // 4) routed GEMM2: y = h @ w2[e] + b2[e] -> fp32
    mma_gemm2<0><<<dim3(DDIM / 128, TILES_MAX, 1), 512, SMEMSZ>>>(
        (unsigned*)p_hh, (unsigned*)p_hl, 0, 1024,
        (unsigned*)p_w2h, b2, DDIM,
        (float*)p_yb, 0, DDIM, nullptr, nullptr, 0, 0,
        (const int*)p_te, HDIM / 32, DDIM / 128);
    // 5) shared GEMM1: hs[s] = gelu(x @ sw1[s] + sb1[s]) -> packed fp16 hi/lo
    //    A (x) is the SAME for both shared experts -> a_z stride 0.
    mma_gemm2<1><<<dim3(HDIM / 128, MT_S, NSH), 512, SMEMSZ>>>(
        (unsigned*)p_xh, (unsigned*)p_xl, 0, 512,
        (unsigned*)p_s1h, sb1, HDIM,
        nullptr, 0, 0, (unsigned*)p_sh, (unsigned*)p_sl, (long long)NTOK * 1024, 1024,
        nullptr, DDIM / 32, HDIM / 128);
    // 6) shared GEMM2: ys[s] = hs[s] @ sw2[s] + sb2[s] -> fp32
    mma_gemm2<0><<<dim3(DDIM / 128, MT_S, NSH), 512, SMEMSZ>>>(
        (unsigned*)p_sh, (unsigned*)p_sl, (long long)NTOK * 1024, 1024,
        (unsigned*)p_s2h, sb2, DDIM,
        (float*)p_ys, (long long)NTOK * DDIM, DDIM, nullptr, nullptr, 0, 0,
        nullptr, HDIM / 32, DDIM / 128);
    // 7) combine
    combine_kernel<<<(N * (DDIM / 4) + 255) / 256, 256>>>(out, N);
}

// round 15
// speedup vs baseline: 1.3921x; 1.3921x over previous
#include <cuda_runtime.h>
#include <cuda_fp16.h>
#include <math.h>
#include <stdint.h>

// Problem constants: B=4, L=2048 -> N=8192 tokens
#define NTOK 8192
#define DDIM 1024
#define HDIM 2048
#define NEXP 8
#define NSH 2
#define MAXP (2 * NTOK)
#define MAXP_PAD (MAXP + NEXP * 128)  // 17408
#define TILES_MAX (MAXP_PAD / 128)    // 136
#define MT_S (NTOK / 128)             // 64

// GEMM staging geometry (words = 32-bit packed fp16 pairs)
// CTA tile 128x128, BK=64 (32 kpairs). A hi/lo + B: 128 rows x 32 words, stride 36.
#define NSTG 3
#define RSTRIDE 36
#define AH_OFF 0
#define AL_OFF 4608                    // 128*36
#define BH_OFF 9216
#define STG_W 13824                    // words per stage (54KB)
#define SMEMSZ (NSTG * STG_W * 4)      // 165888 bytes

// ------------------------- scratch (__device__ globals) -------------------------
__device__ unsigned g_x_hi [(size_t)NTOK * 512];
__device__ unsigned g_x_lo [(size_t)NTOK * 512];
__device__ unsigned g_xg_hi[(size_t)MAXP_PAD * 512];
__device__ unsigned g_xg_lo[(size_t)MAXP_PAD * 512];
__device__ unsigned g_h_hi [(size_t)MAXP_PAD * 1024];
__device__ unsigned g_h_lo [(size_t)MAXP_PAD * 1024];
__device__ unsigned g_hs_hi[(size_t)NSH * NTOK * 1024];
__device__ unsigned g_hs_lo[(size_t)NSH * NTOK * 1024];
__device__ unsigned g_w1t_hi[(size_t)NEXP * 512 * HDIM];
__device__ unsigned g_w2t_hi[(size_t)NEXP * 1024 * DDIM];
__device__ unsigned g_s1t_hi[(size_t)NSH * 512 * HDIM];
__device__ unsigned g_s2t_hi[(size_t)NSH * 1024 * DDIM];
__device__ float g_ybuf[(size_t)MAXP_PAD * DDIM];
__device__ float g_ys[(size_t)NSH * NTOK * DDIM];
__device__ int   g_pair_token[MAXP_PAD];
__device__ int   g_slot_of[MAXP];
__device__ float g_gate[MAXP];
__device__ int   g_topi[MAXP];
__device__ int   g_tile_expert[TILES_MAX];

// ------------------------- helpers -------------------------
__device__ __forceinline__ uint32_t smem_u32(const void* p) {
    uint32_t a;
    asm("{ .reg .u64 t; cvta.to.shared.u64 t, %1; cvt.u32.u64 %0, t; }" : "=r"(a) : "l"(p));
    return a;
}
__device__ __forceinline__ void cp16(uint32_t dst, const void* src) {
    asm volatile("cp.async.cg.shared.global [%0], [%1], 16;" :: "r"(dst), "l"(src) : "memory");
}
#define CP_COMMIT() asm volatile("cp.async.commit_group;" ::: "memory")
#define CP_WAIT1() asm volatile("cp.async.wait_group 1;" ::: "memory")

#define LDSM4(r0, r1, r2, r3, addr)                                           \
    asm volatile("ldmatrix.sync.aligned.m8n8.x4.shared.b16 {%0,%1,%2,%3},[%4];" \
                 : "=r"(r0), "=r"(r1), "=r"(r2), "=r"(r3) : "r"(addr))
#define LDSM2(r0, r1, addr)                                                   \
    asm volatile("ldmatrix.sync.aligned.m8n8.x2.shared.b16 {%0,%1},[%2];"     \
                 : "=r"(r0), "=r"(r1) : "r"(addr))

// fp16 split: x = hi + lo; hi captures ~12 bits, lo the next ~12 (A operand)
__device__ __forceinline__ void cvt_pair_h(float x0, float x1, unsigned& hi, unsigned& lo) {
    __half h0 = __float2half_rn(x0);
    __half h1 = __float2half_rn(x1);
    float r0 = x0 - __half2float(h0);
    float r1 = x1 - __half2float(h1);
    __half l0 = __float2half_rn(r0);
    __half l1 = __float2half_rn(r1);
    hi = (unsigned)__half_as_ushort(h0) | ((unsigned)__half_as_ushort(h1) << 16);
    lo = (unsigned)__half_as_ushort(l0) | ((unsigned)__half_as_ushort(l1) << 16);
}
// fp16 single (B operand)
__device__ __forceinline__ unsigned cvt_one_h(float x0, float x1) {
    return (unsigned)__half_as_ushort(__float2half_rn(x0)) |
           ((unsigned)__half_as_ushort(__float2half_rn(x1)) << 16);
}

#define MMA_F16(accp, a, b)                                                   \
    asm volatile(                                                             \
        "mma.sync.aligned.m16n8k16.row.col.f32.f16.f16.f32 "                  \
        "{%0,%1,%2,%3},{%4,%5,%6,%7},{%8,%9},{%0,%1,%2,%3};"                  \
        : "+f"((accp)[0]), "+f"((accp)[1]), "+f"((accp)[2]), "+f"((accp)[3])  \
        : "r"((a)[0]), "r"((a)[1]), "r"((a)[2]), "r"((a)[3]),                 \
          "r"((b)[0]), "r"((b)[1]))

// ------------------------- router -------------------------
__global__ void router_kernel(const float* __restrict__ x, const float* __restrict__ rw,
                              const float* __restrict__ rb, int N) {
    int w = (blockIdx.x * blockDim.x + threadIdx.x) >> 5;
    int lane = threadIdx.x & 31;
    if (w >= N) return;
    const float* xr = x + (size_t)w * DDIM;
    float acc[NEXP];
#pragma unroll
    for (int e = 0; e < NEXP; e++) acc[e] = 0.f;
    for (int d = lane; d < DDIM; d += 32) {
        float xv = xr[d];
        const float* r = rw + (size_t)d * NEXP;
#pragma unroll
        for (int e = 0; e < NEXP; e++) acc[e] = fmaf(xv, r[e], acc[e]);
    }
#pragma unroll
    for (int e = 0; e < NEXP; e++)
        for (int o = 16; o > 0; o >>= 1) acc[e] += __shfl_xor_sync(0xffffffffu, acc[e], o);
    if (lane == 0) {
        float v0 = -1e30f, v1 = -1e30f;
        int i0 = 0, i1 = 0;
#pragma unroll
        for (int e = 0; e < NEXP; e++) {
            float v = acc[e] + rb[e];
            if (v > v0) { v1 = v0; i1 = i0; v0 = v; i0 = e; }
            else if (v > v1) { v1 = v; i1 = e; }
        }
        float p1 = expf(v1 - v0);
        float inv = 1.0f / (1.0f + p1);
        g_topi[2 * w] = i0; g_topi[2 * w + 1] = i1;
        g_gate[2 * w] = inv; g_gate[2 * w + 1] = p1 * inv;
    }
}

// ------------------------- bucketing -------------------------
__global__ void bucket_kernel(int N) {
    __shared__ int s_cnt[NEXP];
    __shared__ int s_off[NEXP + 1];
    __shared__ int s_c2[NEXP];
    int tid = threadIdx.x;
    if (tid < NEXP) { s_cnt[tid] = 0; s_c2[tid] = 0; }
    __syncthreads();
    int P = 2 * N;
    for (int p = tid; p < P; p += blockDim.x) atomicAdd(&s_cnt[g_topi[p]], 1);
    for (int i = tid; i < MAXP_PAD; i += blockDim.x) g_pair_token[i] = -1;
    __syncthreads();
    if (tid == 0) {
        int o = 0;
        for (int e = 0; e < NEXP; e++) { s_off[e] = o; o += ((s_cnt[e] + 127) >> 7) << 7; }
        s_off[NEXP] = o;
        int total = o >> 7;
        for (int t = 0; t < TILES_MAX; t++) {
            int ex = -1;
            if (t < total) {
                int s = t << 7;
                for (int e = 0; e < NEXP; e++)
                    if (s >= s_off[e] && s < s_off[e + 1]) ex = e;
            }
            g_tile_expert[t] = ex;
        }
    }
    __syncthreads();
    for (int p = tid; p < P; p += blockDim.x) {
        int e = g_topi[p];
        int pos = atomicAdd(&s_c2[e], 1);
        int slot = s_off[e] + pos;
        g_pair_token[slot] = p >> 1;
        g_slot_of[p] = slot;
    }
}

// ------------------------- operand pre-conversion -------------------------
// x (fp32 row-major) -> packed fp16 hi/lo words, row-major [n][D/2]
__global__ void pack_x_kernel(const float* __restrict__ x) {
    size_t idx = (size_t)blockIdx.x * blockDim.x + threadIdx.x;
    if (idx >= (size_t)NTOK * 512) return;
    float2 v = *(const float2*)(x + 2 * idx);
    unsigned h, l; cvt_pair_h(v.x, v.y, h, l);
    g_x_hi[idx] = h; g_x_lo[idx] = l;
}
// gathered x by slot -> [slot][D/2]
__global__ void pack_xg_kernel(const float* __restrict__ x) {
    size_t idx = (size_t)blockIdx.x * blockDim.x + threadIdx.x;
    if (idx >= (size_t)MAXP_PAD * 512) return;
    int slot = (int)(idx >> 9), w = (int)(idx & 511);
    int tok = g_pair_token[slot];
    float2 v = (tok >= 0) ? *(const float2*)(x + (size_t)tok * DDIM + 2 * w)
                          : make_float2(0.f, 0.f);
    unsigned h, l; cvt_pair_h(v.x, v.y, h, l);
    g_xg_hi[idx] = h; g_xg_lo[idx] = l;
}
// W [Z][K][N] fp32 -> n-major blocks [(z*NT+nt)*KC + kc][n 128][kpair 16], single fp16
// (kc = 32-element k-chunks; two consecutive kc blocks form one BK=64 slab)
__global__ void wt_kernel(const float* __restrict__ W,
                          unsigned* __restrict__ oh,
                          int K, int N) {
    __shared__ float t[64][33];
    int z = blockIdx.z;
    const float* Wz = W + (size_t)z * K * N;
    int k0 = blockIdx.y * 64, n0 = blockIdx.x * 32;
    int tx = threadIdx.x, ty = threadIdx.y;
#pragma unroll
    for (int i = 0; i < 8; i++) {
        int k = ty + i * 8;
        t[k][tx] = Wz[(size_t)(k0 + k) * N + n0 + tx];
    }
    __syncthreads();
    int tid = ty * 32 + tx;
    int nl = tid >> 3, w8 = tid & 7;
    int NT = N >> 7, KC = K >> 5;
    int nabs = n0 + nl, nt = nabs >> 7, nin = nabs & 127;
#pragma unroll
    for (int kcb = 0; kcb < 2; kcb++) {
        int kc = (k0 >> 5) + kcb;
        size_t base = ((size_t)(z * NT + nt) * KC + kc) * 2048 + (size_t)nin * 16;
#pragma unroll
        for (int j = 0; j < 2; j++) {
            int kp = w8 * 2 + j;
            int kloc = kcb * 32 + kp * 2;
            oh[base + kp] = cvt_one_h(t[kloc][nl], t[kloc + 1][nl]);
        }
    }
}

// ------------------------- mma.sync GEMM: 128x128 tile, 512 threads, BK=64 -------------------------
// 16 warps (4M x 4N), 32x32 C per warp, fp16x2 on A (hi+lo) x single-fp16 B.
// BK=64: 4 k16-steps per k-block -> half the syncs/waits of BK=32. 3-stage cp.async.
// GELU=0: C fp32 += bias. GELU=1: gelu(C+bias) -> packed fp16 hi/lo words (A-format).
template <int GELU>
__global__ void __launch_bounds__(512, 1)
mma_gemm2(const unsigned* __restrict__ Ah, const unsigned* __restrict__ Al,
          long long a_z, int a_ld,
          const unsigned* __restrict__ Bh,
          const float* __restrict__ bias_base, int bias_stride,
          float* __restrict__ Cf, long long c_z, int c_ld,
          unsigned* __restrict__ Oh, unsigned* __restrict__ Ol,
          long long o_z, int o_ld,
          const int* __restrict__ te, int nKb, int NTtot) {
    int nt = blockIdx.x, mt = blockIdx.y, z = blockIdx.z;
    int expert = te ? te[mt] : z;
    if (expert < 0) return;

    extern __shared__ unsigned smw[];
    uint32_t sb = smem_u32(smw);
    int tid = threadIdx.x, lane = tid & 31, wid = tid >> 5;
    int wm = (wid & 3) * 32, wn = (wid >> 2) * 32;
    int mBase = mt * 128;

    const unsigned* Abase_h = Ah + (size_t)z * a_z + (size_t)mBase * a_ld;
    const unsigned* Abase_l = Al + (size_t)z * a_z + (size_t)mBase * a_ld;
    const unsigned* Bbase_h = Bh + (size_t)(expert * NTtot + nt) * (size_t)nKb * 4096;

    // copy decode: each array 128 rows x 32 words = 1024 x 16B chunks; 2 chunks/thread/array
    int rowC = tid >> 2, cpair = (tid & 3) * 2;

    auto issue = [&](int kb) {
        uint32_t st = sb + (uint32_t)((kb % NSTG) * STG_W) * 4;
#pragma unroll
        for (int cc = 0; cc < 2; cc++) {
            int c = cpair + cc;                 // chunk 0..7 (4 words each)
            uint32_t so = (uint32_t)(rowC * RSTRIDE + c * 4) * 4;
            const unsigned* ag = Abase_h + (size_t)rowC * a_ld + kb * 32 + c * 4;
            cp16(st + AH_OFF * 4 + so, ag);
            cp16(st + AL_OFF * 4 + so, Abase_l + (size_t)rowC * a_ld + kb * 32 + c * 4);
            const unsigned* bg = Bbase_h + (size_t)kb * 4096 +
                                 (c < 4 ? (size_t)rowC * 16 + c * 4
                                        : 2048 + (size_t)rowC * 16 + (c - 4) * 4);
            cp16(st + BH_OFF * 4 + so, bg);
        }
    };

    float acc[2][4][4];
#pragma unroll
    for (int a = 0; a < 2; a++)
#pragma unroll
        for (int b = 0; b < 4; b++)
#pragma unroll
            for (int c = 0; c < 4; c++) acc[a][b][c] = 0.f;

    // prologue: 2 stages in flight
    issue(0); CP_COMMIT();
    if (nKb > 1) issue(1);
    CP_COMMIT();

    // ldmatrix per-thread base offsets (bytes)
    uint32_t a_off = (uint32_t)((wm + (lane & 15)) * RSTRIDE + (lane >> 4) * 4) * 4;
    uint32_t b_off = (uint32_t)((wn + (lane & 7)) * RSTRIDE + ((lane >> 3) & 1) * 4) * 4;

    for (int kb = 0; kb < nKb; kb++) {
        CP_WAIT1();
        __syncthreads();
        int nx = kb + 2;
        if (nx < nKb) issue(nx);
        CP_COMMIT();

        uint32_t stg = sb + (uint32_t)((kb % NSTG) * STG_W) * 4;
        uint32_t aH = stg + AH_OFF * 4 + a_off;
        uint32_t aL = stg + AL_OFF * 4 + a_off;
        uint32_t bH = stg + BH_OFF * 4 + b_off;
#pragma unroll
        for (int ks = 0; ks < 4; ks++) {
            unsigned ah[2][4], al[2][4];
#pragma unroll
            for (int m2 = 0; m2 < 2; m2++) {
                uint32_t o = m2 * (16 * RSTRIDE * 4) + ks * 32;
                LDSM4(ah[m2][0], ah[m2][1], ah[m2][2], ah[m2][3], aH + o);
                LDSM4(al[m2][0], al[m2][1], al[m2][2], al[m2][3], aL + o);
            }
#pragma unroll
            for (int n8 = 0; n8 < 4; n8++) {
                unsigned bh[2];
                uint32_t o = n8 * (8 * RSTRIDE * 4) + ks * 32;
                LDSM2(bh[0], bh[1], bH + o);
#pragma unroll
                for (int m2 = 0; m2 < 2; m2++) MMA_F16(acc[m2][n8], ah[m2], bh);
#pragma unroll
                for (int m2 = 0; m2 < 2; m2++) MMA_F16(acc[m2][n8], al[m2], bh);
            }
        }
    }

    // epilogue
    const float* bias = bias_base + (size_t)expert * bias_stride + nt * 128;
#pragma unroll
    for (int m2 = 0; m2 < 2; m2++) {
#pragma unroll
        for (int n8 = 0; n8 < 4; n8++) {
            int row0 = mBase + wm + m2 * 16 + (lane >> 2);
            int c0 = wn + n8 * 8 + (lane & 3) * 2;
            float b0 = bias[c0], b1 = bias[c0 + 1];
            float v0 = acc[m2][n8][0] + b0;
            float v1 = acc[m2][n8][1] + b1;
            float v2 = acc[m2][n8][2] + b0;
            float v3 = acc[m2][n8][3] + b1;
            if (GELU) {
                v0 = 0.5f * v0 * (1.0f + erff(v0 * 0.70710678118654752f));
                v1 = 0.5f * v1 * (1.0f + erff(v1 * 0.70710678118654752f));
                v2 = 0.5f * v2 * (1.0f + erff(v2 * 0.70710678118654752f));
                v3 = 0.5f * v3 * (1.0f + erff(v3 * 0.70710678118654752f));
                unsigned h0, l0, h1, l1;
                cvt_pair_h(v0, v1, h0, l0);
                cvt_pair_h(v2, v3, h1, l1);
                size_t w = (size_t)((nt * 128 + c0) >> 1);
                size_t b0i = (size_t)z * o_z + (size_t)row0 * o_ld + w;
                size_t b1i = b0i + (size_t)8 * o_ld;
                Oh[b0i] = h0; Ol[b0i] = l0;
                Oh[b1i] = h1; Ol[b1i] = l1;
            } else {
                size_t base = (size_t)z * c_z + (size_t)row0 * c_ld + nt * 128 + c0;
                *(float2*)&Cf[base] = make_float2(v0, v1);
                *(float2*)&Cf[base + (size_t)8 * c_ld] = make_float2(v2, v3);
            }
        }
    }
}

// ------------------------- final combine -------------------------
__global__ void combine_kernel(float* __restrict__ out, int N) {
    int idx = blockIdx.x * blockDim.x + threadIdx.x;
    int total = N * (DDIM / 4);
    if (idx >= total) return;
    int n = idx / (DDIM / 4);
    int d = (idx % (DDIM / 4)) * 4;
    const float4 s0 = *(const float4*)&g_ys[(size_t)n * DDIM + d];
    const float4 s1 = *(const float4*)&g_ys[(size_t)N * DDIM + (size_t)n * DDIM + d];
    int sl0 = g_slot_of[2 * n], sl1 = g_slot_of[2 * n + 1];
    float w0 = g_gate[2 * n], w1 = g_gate[2 * n + 1];
    const float4 y0 = *(const float4*)&g_ybuf[(size_t)sl0 * DDIM + d];
    const float4 y1 = *(const float4*)&g_ybuf[(size_t)sl1 * DDIM + d];
    const float inv_s = 1.0f / NSH;
    float4 o;
    o.x = inv_s * (s0.x + s1.x) + w0 * y0.x + w1 * y1.x;
    o.y = inv_s * (s0.y + s1.y) + w0 * y0.y + w1 * y1.y;
    o.z = inv_s * (s0.z + s1.z) + w0 * y0.z + w1 * y1.z;
    o.w = inv_s * (s0.w + s1.w) + w0 * y0.w + w1 * y1.w;
    *(float4*)&out[(size_t)n * DDIM + d] = o;
}

// ------------------------- launch -------------------------
#define SYM(p, s) void* p; cudaGetSymbolAddress(&p, s)

extern "C" void kernel_launch(void* const* d_in, const int* in_sizes, int n_in,
                              void* d_out, int out_size) {
    const float* x   = (const float*)d_in[0];
    const float* rw  = (const float*)d_in[1];
    const float* rb  = (const float*)d_in[2];
    const float* w1  = (const float*)d_in[3];
    const float* b1  = (const float*)d_in[4];
    const float* w2  = (const float*)d_in[5];
    const float* b2  = (const float*)d_in[6];
    const float* sw1 = (const float*)d_in[7];
    const float* sb1 = (const float*)d_in[8];
    const float* sw2 = (const float*)d_in[9];
    const float* sb2 = (const float*)d_in[10];
    float* out = (float*)d_out;
    int N = in_sizes[0] / DDIM;

    cudaFuncSetAttribute(mma_gemm2<0>, cudaFuncAttributeMaxDynamicSharedMemorySize, SMEMSZ);
    cudaFuncSetAttribute(mma_gemm2<1>, cudaFuncAttributeMaxDynamicSharedMemorySize, SMEMSZ);

    SYM(p_xh, g_x_hi);    SYM(p_xl, g_x_lo);
    SYM(p_gh, g_xg_hi);   SYM(p_gl, g_xg_lo);
    SYM(p_hh, g_h_hi);    SYM(p_hl, g_h_lo);
    SYM(p_sh, g_hs_hi);   SYM(p_sl, g_hs_lo);
    SYM(p_w1h, g_w1t_hi);
    SYM(p_w2h, g_w2t_hi);
    SYM(p_s1h, g_s1t_hi);
    SYM(p_s2h, g_s2t_hi);
    SYM(p_yb, g_ybuf);    SYM(p_ys, g_ys);
    SYM(p_te, g_tile_expert);

    // 1) router + bucketing
    router_kernel<<<(N + 7) / 8, 256>>>(x, rw, rb, N);
    bucket_kernel<<<1, 256>>>(N);
    // 2) operand pre-conversion
    pack_x_kernel<<<(NTOK * 512 + 255) / 256, 256>>>(x);
    pack_xg_kernel<<<(MAXP_PAD * 512 + 255) / 256, 256>>>(x);
    dim3 tb(32, 8);
    wt_kernel<<<dim3(HDIM / 32, DDIM / 64, NEXP), tb>>>(w1, (unsigned*)p_w1h, DDIM, HDIM);
    wt_kernel<<<dim3(DDIM / 32, HDIM / 64, NEXP), tb>>>(w2, (unsigned*)p_w2h, HDIM, DDIM);
    wt_kernel<<<dim3(HDIM / 32, DDIM / 64, NSH), tb>>>(sw1, (unsigned*)p_s1h, DDIM, HDIM);
    wt_kernel<<<dim3(DDIM / 32, HDIM / 64, NSH), tb>>>(sw2, (unsigned*)p_s2h, HDIM, DDIM);
    // 3) routed GEMM1: h = gelu(xg @ w1[e] + b1[e]) -> packed fp16 hi/lo (A-format)
    mma_gemm2<1><<<dim3(HDIM / 128, TILES_MAX, 1), 512, SMEMSZ>>>(
        (unsigned*)p_gh, (unsigned*)p_gl, 0, 512,
        (unsigned*)p_w1h, b1, HDIM,
        nullptr, 0, 0, (unsigned*)p_hh, (unsigned*)p_hl, 0, 1024,
        (const int*)p_te, DDIM / 64, HDIM / 128);
    // 4) routed GEMM2: y = h @ w2[e] + b2[e] -> fp32
    mma_gemm2<0><<<dim3(DDIM / 128, TILES_MAX, 1), 512, SMEMSZ>>>(
        (unsigned*)p_hh, (unsigned*)p_hl, 0, 1024,
        (unsigned*)p_w2h, b2, DDIM,
        (float*)p_yb, 0, DDIM, nullptr, nullptr, 0, 0,
        (const int*)p_te, HDIM / 64, DDIM / 128);
    // 5) shared GEMM1: hs[s] = gelu(x @ sw1[s] + sb1[s]) -> packed fp16 hi/lo
    //    A (x) is the SAME for both shared experts -> a_z stride 0.
    mma_gemm2<1><<<dim3(HDIM / 128, MT_S, NSH), 512, SMEMSZ>>>(
        (unsigned*)p_xh, (unsigned*)p_xl, 0, 512,
        (unsigned*)p_s1h, sb1, HDIM,
        nullptr, 0, 0, (unsigned*)p_sh, (unsigned*)p_sl, (long long)NTOK * 1024, 1024,
        nullptr, DDIM / 64, HDIM / 128);
    // 6) shared GEMM2: ys[s] = hs[s] @ sw2[s] + sb2[s] -> fp32
    mma_gemm2<0><<<dim3(DDIM / 128, MT_S, NSH), 512, SMEMSZ>>>(
        (unsigned*)p_sh, (unsigned*)p_sl, (long long)NTOK * 1024, 1024,
        (unsigned*)p_s2h, sb2, DDIM,
        (float*)p_ys, (long long)NTOK * DDIM, DDIM, nullptr, nullptr, 0, 0,
        nullptr, HDIM / 64, DDIM / 128);
    // 7) combine
    combine_kernel<<<(N * (DDIM / 4) + 255) / 256, 256>>>(out, N);
}

// round 16
// speedup vs baseline: 2.1090x; 1.5150x over previous
#include <cuda_runtime.h>
#include <cuda_fp16.h>
#include <math.h>
#include <stdint.h>

// Problem constants: B=4, L=2048 -> N=8192 tokens
#define NTOK 8192
#define DDIM 1024
#define HDIM 2048
#define NEXP 8
#define NSH 2
#define MAXP (2 * NTOK)
#define MAXP_PAD (MAXP + NEXP * 128)  // 17408
#define TILES_MAX (MAXP_PAD / 128)    // 136
#define MT_S (NTOK / 128)             // 64

// GEMM staging geometry (words = 32-bit packed fp16 pairs)
// CTA tile 128x128, BK=64 (32 kpairs). A + B: 128 rows x 32 words, stride 36.
#define NSTG 4
#define RSTRIDE 36
#define AH_OFF 0
#define BH_OFF 4608                    // 128*36
#define STG_W 9216                     // words per stage (36KB)
#define SMEMSZ (NSTG * STG_W * 4)      // 147456 bytes

// ------------------------- scratch (__device__ globals) -------------------------
__device__ unsigned g_x_h [(size_t)NTOK * 512];
__device__ unsigned g_xg_h[(size_t)MAXP_PAD * 512];
__device__ unsigned g_h_h [(size_t)MAXP_PAD * 1024];
__device__ unsigned g_hs_h[(size_t)NSH * NTOK * 1024];
__device__ unsigned g_w1t [(size_t)NEXP * 512 * HDIM];
__device__ unsigned g_w2t [(size_t)NEXP * 1024 * DDIM];
__device__ unsigned g_s1t [(size_t)NSH * 512 * HDIM];
__device__ unsigned g_s2t [(size_t)NSH * 1024 * DDIM];
__device__ float g_ybuf[(size_t)MAXP_PAD * DDIM];
__device__ float g_ys[(size_t)NSH * NTOK * DDIM];
__device__ int   g_pair_token[MAXP_PAD];
__device__ int   g_slot_of[MAXP];
__device__ float g_gate[MAXP];
__device__ int   g_topi[MAXP];
__device__ int   g_tile_expert[TILES_MAX];

// ------------------------- helpers -------------------------
__device__ __forceinline__ uint32_t smem_u32(const void* p) {
    uint32_t a;
    asm("{ .reg .u64 t; cvta.to.shared.u64 t, %1; cvt.u32.u64 %0, t; }" : "=r"(a) : "l"(p));
    return a;
}
__device__ __forceinline__ void cp16(uint32_t dst, const void* src) {
    asm volatile("cp.async.cg.shared.global [%0], [%1], 16;" :: "r"(dst), "l"(src) : "memory");
}
#define CP_COMMIT() asm volatile("cp.async.commit_group;" ::: "memory")
#define CP_WAIT2() asm volatile("cp.async.wait_group 2;" ::: "memory")

#define LDSM4(r0, r1, r2, r3, addr)                                           \
    asm volatile("ldmatrix.sync.aligned.m8n8.x4.shared.b16 {%0,%1,%2,%3},[%4];" \
                 : "=r"(r0), "=r"(r1), "=r"(r2), "=r"(r3) : "r"(addr))
#define LDSM2(r0, r1, addr)                                                   \
    asm volatile("ldmatrix.sync.aligned.m8n8.x2.shared.b16 {%0,%1},[%2];"     \
                 : "=r"(r0), "=r"(r1) : "r"(addr))

// fp16 pack (pair of floats -> one b32 word)
__device__ __forceinline__ unsigned cvt_one_h(float x0, float x1) {
    return (unsigned)__half_as_ushort(__float2half_rn(x0)) |
           ((unsigned)__half_as_ushort(__float2half_rn(x1)) << 16);
}

#define MMA_F16(accp, a, b)                                                   \
    asm volatile(                                                             \
        "mma.sync.aligned.m16n8k16.row.col.f32.f16.f16.f32 "                  \
        "{%0,%1,%2,%3},{%4,%5,%6,%7},{%8,%9},{%0,%1,%2,%3};"                  \
        : "+f"((accp)[0]), "+f"((accp)[1]), "+f"((accp)[2]), "+f"((accp)[3])  \
        : "r"((a)[0]), "r"((a)[1]), "r"((a)[2]), "r"((a)[3]),                 \
          "r"((b)[0]), "r"((b)[1]))

// ------------------------- router -------------------------
__global__ void router_kernel(const float* __restrict__ x, const float* __restrict__ rw,
                              const float* __restrict__ rb, int N) {
    int w = (blockIdx.x * blockDim.x + threadIdx.x) >> 5;
    int lane = threadIdx.x & 31;
    if (w >= N) return;
    const float* xr = x + (size_t)w * DDIM;
    float acc[NEXP];
#pragma unroll
    for (int e = 0; e < NEXP; e++) acc[e] = 0.f;
    for (int d = lane; d < DDIM; d += 32) {
        float xv = xr[d];
        const float* r = rw + (size_t)d * NEXP;
#pragma unroll
        for (int e = 0; e < NEXP; e++) acc[e] = fmaf(xv, r[e], acc[e]);
    }
#pragma unroll
    for (int e = 0; e < NEXP; e++)
        for (int o = 16; o > 0; o >>= 1) acc[e] += __shfl_xor_sync(0xffffffffu, acc[e], o);
    if (lane == 0) {
        float v0 = -1e30f, v1 = -1e30f;
        int i0 = 0, i1 = 0;
#pragma unroll
        for (int e = 0; e < NEXP; e++) {
            float v = acc[e] + rb[e];
            if (v > v0) { v1 = v0; i1 = i0; v0 = v; i0 = e; }
            else if (v > v1) { v1 = v; i1 = e; }
        }
        float p1 = expf(v1 - v0);
        float inv = 1.0f / (1.0f + p1);
        g_topi[2 * w] = i0; g_topi[2 * w + 1] = i1;
        g_gate[2 * w] = inv; g_gate[2 * w + 1] = p1 * inv;
    }
}

// ------------------------- bucketing -------------------------
__global__ void bucket_kernel(int N) {
    __shared__ int s_cnt[NEXP];
    __shared__ int s_off[NEXP + 1];
    __shared__ int s_c2[NEXP];
    int tid = threadIdx.x;
    if (tid < NEXP) { s_cnt[tid] = 0; s_c2[tid] = 0; }
    __syncthreads();
    int P = 2 * N;
    for (int p = tid; p < P; p += blockDim.x) atomicAdd(&s_cnt[g_topi[p]], 1);
    for (int i = tid; i < MAXP_PAD; i += blockDim.x) g_pair_token[i] = -1;
    __syncthreads();
    if (tid == 0) {
        int o = 0;
        for (int e = 0; e < NEXP; e++) { s_off[e] = o; o += ((s_cnt[e] + 127) >> 7) << 7; }
        s_off[NEXP] = o;
        int total = o >> 7;
        for (int t = 0; t < TILES_MAX; t++) {
            int ex = -1;
            if (t < total) {
                int s = t << 7;
                for (int e = 0; e < NEXP; e++)
                    if (s >= s_off[e] && s < s_off[e + 1]) ex = e;
            }
            g_tile_expert[t] = ex;
        }
    }
    __syncthreads();
    for (int p = tid; p < P; p += blockDim.x) {
        int e = g_topi[p];
        int pos = atomicAdd(&s_c2[e], 1);
        int slot = s_off[e] + pos;
        g_pair_token[slot] = p >> 1;
        g_slot_of[p] = slot;
    }
}

// ------------------------- operand pre-conversion -------------------------
// x (fp32 row-major) -> packed fp16 words, row-major [n][D/2]
__global__ void pack_x_kernel(const float* __restrict__ x) {
    size_t idx = (size_t)blockIdx.x * blockDim.x + threadIdx.x;
    if (idx >= (size_t)NTOK * 512) return;
    float2 v = *(const float2*)(x + 2 * idx);
    g_x_h[idx] = cvt_one_h(v.x, v.y);
}
// gathered x by slot -> [slot][D/2]
__global__ void pack_xg_kernel(const float* __restrict__ x) {
    size_t idx = (size_t)blockIdx.x * blockDim.x + threadIdx.x;
    if (idx >= (size_t)MAXP_PAD * 512) return;
    int slot = (int)(idx >> 9), w = (int)(idx & 511);
    int tok = g_pair_token[slot];
    float2 v = (tok >= 0) ? *(const float2*)(x + (size_t)tok * DDIM + 2 * w)
                          : make_float2(0.f, 0.f);
    g_xg_h[idx] = cvt_one_h(v.x, v.y);
}
// W [Z][K][N] fp32 -> n-major blocks [(z*NT+nt)*KC + kc][n 128][kpair 16], single fp16
// (kc = 32-element k-chunks; two consecutive kc blocks form one BK=64 slab)
__global__ void wt_kernel(const float* __restrict__ W,
                          unsigned* __restrict__ oh,
                          int K, int N) {
    __shared__ float t[64][33];
    int z = blockIdx.z;
    const float* Wz = W + (size_t)z * K * N;
    int k0 = blockIdx.y * 64, n0 = blockIdx.x * 32;
    int tx = threadIdx.x, ty = threadIdx.y;
#pragma unroll
    for (int i = 0; i < 8; i++) {
        int k = ty + i * 8;
        t[k][tx] = Wz[(size_t)(k0 + k) * N + n0 + tx];
    }
    __syncthreads();
    int tid = ty * 32 + tx;
    int nl = tid >> 3, w8 = tid & 7;
    int NT = N >> 7, KC = K >> 5;
    int nabs = n0 + nl, nt = nabs >> 7, nin = nabs & 127;
#pragma unroll
    for (int kcb = 0; kcb < 2; kcb++) {
        int kc = (k0 >> 5) + kcb;
        size_t base = ((size_t)(z * NT + nt) * KC + kc) * 2048 + (size_t)nin * 16;
#pragma unroll
        for (int j = 0; j < 2; j++) {
            int kp = w8 * 2 + j;
            int kloc = kcb * 32 + kp * 2;
            oh[base + kp] = cvt_one_h(t[kloc][nl], t[kloc + 1][nl]);
        }
    }
}

// ------------------------- mma.sync GEMM: 128x128 tile, 512 threads, BK=64, pure fp16 -------------------------
// 16 warps (4M x 4N), 32x32 C per warp, single-fp16 A x single-fp16 B, fp32 accum.
// BK=64: 4 k16-steps per k-block. 4-stage cp.async pipeline, ldmatrix fragment loads.
// GELU=0: C fp32 += bias. GELU=1: gelu(C+bias) -> packed fp16 words (A-format).
template <int GELU>
__global__ void __launch_bounds__(512, 1)
mma_gemm2(const unsigned* __restrict__ Ah, long long a_z, int a_ld,
          const unsigned* __restrict__ Bh,
          const float* __restrict__ bias_base, int bias_stride,
          float* __restrict__ Cf, long long c_z, int c_ld,
          unsigned* __restrict__ Oh, long long o_z, int o_ld,
          const int* __restrict__ te, int nKb, int NTtot) {
    int nt = blockIdx.x, mt = blockIdx.y, z = blockIdx.z;
    int expert = te ? te[mt] : z;
    if (expert < 0) return;

    extern __shared__ unsigned smw[];
    uint32_t sb = smem_u32(smw);
    int tid = threadIdx.x, lane = tid & 31, wid = tid >> 5;
    int wm = (wid & 3) * 32, wn = (wid >> 2) * 32;
    int mBase = mt * 128;

    const unsigned* Abase = Ah + (size_t)z * a_z + (size_t)mBase * a_ld;
    const unsigned* Bbase = Bh + (size_t)(expert * NTtot + nt) * (size_t)nKb * 4096;

    // copy decode: each array 128 rows x 32 words = 1024 x 16B chunks; 2 chunks/thread/array
    int rowC = tid >> 2, cpair = (tid & 3) * 2;

    auto issue = [&](int kb) {
        uint32_t st = sb + (uint32_t)((kb & (NSTG - 1)) * STG_W) * 4;
#pragma unroll
        for (int cc = 0; cc < 2; cc++) {
            int c = cpair + cc;                 // chunk 0..7 (4 words each)
            uint32_t so = (uint32_t)(rowC * RSTRIDE + c * 4) * 4;
            cp16(st + AH_OFF * 4 + so, Abase + (size_t)rowC * a_ld + kb * 32 + c * 4);
            const unsigned* bg = Bbase + (size_t)kb * 4096 +
                                 (c < 4 ? (size_t)rowC * 16 + c * 4
                                        : 2048 + (size_t)rowC * 16 + (c - 4) * 4);
            cp16(st + BH_OFF * 4 + so, bg);
        }
    };

    float acc[2][4][4];
#pragma unroll
    for (int a = 0; a < 2; a++)
#pragma unroll
        for (int b = 0; b < 4; b++)
#pragma unroll
            for (int c = 0; c < 4; c++) acc[a][b][c] = 0.f;

    // prologue: 3 stages in flight
#pragma unroll
    for (int s = 0; s < NSTG - 1; s++) {
        if (s < nKb) issue(s);
        CP_COMMIT();
    }

    // ldmatrix per-thread base offsets (bytes)
    uint32_t a_off = (uint32_t)((wm + (lane & 15)) * RSTRIDE + (lane >> 4) * 4) * 4;
    uint32_t b_off = (uint32_t)((wn + (lane & 7)) * RSTRIDE + ((lane >> 3) & 1) * 4) * 4;

    for (int kb = 0; kb < nKb; kb++) {
        CP_WAIT2();
        __syncthreads();
        int nx = kb + NSTG - 1;
        if (nx < nKb) issue(nx);
        CP_COMMIT();

        uint32_t stg = sb + (uint32_t)((kb & (NSTG - 1)) * STG_W) * 4;
        uint32_t aH = stg + AH_OFF * 4 + a_off;
        uint32_t bH = stg + BH_OFF * 4 + b_off;
#pragma unroll
        for (int ks = 0; ks < 4; ks++) {
            unsigned ah[2][4];
#pragma unroll
            for (int m2 = 0; m2 < 2; m2++) {
                uint32_t o = m2 * (16 * RSTRIDE * 4) + ks * 32;
                LDSM4(ah[m2][0], ah[m2][1], ah[m2][2], ah[m2][3], aH + o);
            }
#pragma unroll
            for (int n8 = 0; n8 < 4; n8++) {
                unsigned bh[2];
                uint32_t o = n8 * (8 * RSTRIDE * 4) + ks * 32;
                LDSM2(bh[0], bh[1], bH + o);
#pragma unroll
                for (int m2 = 0; m2 < 2; m2++) MMA_F16(acc[m2][n8], ah[m2], bh);
            }
        }
    }

    // epilogue
    const float* bias = bias_base + (size_t)expert * bias_stride + nt * 128;
#pragma unroll
    for (int m2 = 0; m2 < 2; m2++) {
#pragma unroll
        for (int n8 = 0; n8 < 4; n8++) {
            int row0 = mBase + wm + m2 * 16 + (lane >> 2);
            int c0 = wn + n8 * 8 + (lane & 3) * 2;
            float b0 = bias[c0], b1 = bias[c0 + 1];
            float v0 = acc[m2][n8][0] + b0;
            float v1 = acc[m2][n8][1] + b1;
            float v2 = acc[m2][n8][2] + b0;
            float v3 = acc[m2][n8][3] + b1;
            if (GELU) {
                v0 = 0.5f * v0 * (1.0f + erff(v0 * 0.70710678118654752f));
                v1 = 0.5f * v1 * (1.0f + erff(v1 * 0.70710678118654752f));
                v2 = 0.5f * v2 * (1.0f + erff(v2 * 0.70710678118654752f));
                v3 = 0.5f * v3 * (1.0f + erff(v3 * 0.70710678118654752f));
                size_t w = (size_t)((nt * 128 + c0) >> 1);
                size_t b0i = (size_t)z * o_z + (size_t)row0 * o_ld + w;
                size_t b1i = b0i + (size_t)8 * o_ld;
                Oh[b0i] = cvt_one_h(v0, v1);
                Oh[b1i] = cvt_one_h(v2, v3);
            } else {
                size_t base = (size_t)z * c_z + (size_t)row0 * c_ld + nt * 128 + c0;
                *(float2*)&Cf[base] = make_float2(v0, v1);
                *(float2*)&Cf[base + (size_t)8 * c_ld] = make_float2(v2, v3);
            }
        }
    }
}

// ------------------------- final combine -------------------------
__global__ void combine_kernel(float* __restrict__ out, int N) {
    int idx = blockIdx.x * blockDim.x + threadIdx.x;
    int total = N * (DDIM / 4);
    if (idx >= total) return;
    int n = idx / (DDIM / 4);
    int d = (idx % (DDIM / 4)) * 4;
    const float4 s0 = *(const float4*)&g_ys[(size_t)n * DDIM + d];
    const float4 s1 = *(const float4*)&g_ys[(size_t)N * DDIM + (size_t)n * DDIM + d];
    int sl0 = g_slot_of[2 * n], sl1 = g_slot_of[2 * n + 1];
    float w0 = g_gate[2 * n], w1 = g_gate[2 * n + 1];
    const float4 y0 = *(const float4*)&g_ybuf[(size_t)sl0 * DDIM + d];
    const float4 y1 = *(const float4*)&g_ybuf[(size_t)sl1 * DDIM + d];
    const float inv_s = 1.0f / NSH;
    float4 o;
    o.x = inv_s * (s0.x + s1.x) + w0 * y0.x + w1 * y1.x;
    o.y = inv_s * (s0.y + s1.y) + w0 * y0.y + w1 * y1.y;
    o.z = inv_s * (s0.z + s1.z) + w0 * y0.z + w1 * y1.z;
    o.w = inv_s * (s0.w + s1.w) + w0 * y0.w + w1 * y1.w;
    *(float4*)&out[(size_t)n * DDIM + d] = o;
}

// ------------------------- launch -------------------------
#define SYM(p, s) void* p; cudaGetSymbolAddress(&p, s)

extern "C" void kernel_launch(void* const* d_in, const int* in_sizes, int n_in,
                              void* d_out, int out_size) {
    const float* x   = (const float*)d_in[0];
    const float* rw  = (const float*)d_in[1];
    const float* rb  = (const float*)d_in[2];
    const float* w1  = (const float*)d_in[3];
    const float* b1  = (const float*)d_in[4];
    const float* w2  = (const float*)d_in[5];
    const float* b2  = (const float*)d_in[6];
    const float* sw1 = (const float*)d_in[7];
    const float* sb1 = (const float*)d_in[8];
    const float* sw2 = (const float*)d_in[9];
    const float* sb2 = (const float*)d_in[10];
    float* out = (float*)d_out;
    int N = in_sizes[0] / DDIM;

    cudaFuncSetAttribute(mma_gemm2<0>, cudaFuncAttributeMaxDynamicSharedMemorySize, SMEMSZ);
    cudaFuncSetAttribute(mma_gemm2<1>, cudaFuncAttributeMaxDynamicSharedMemorySize, SMEMSZ);

    SYM(p_x, g_x_h);
    SYM(p_g, g_xg_h);
    SYM(p_h, g_h_h);
    SYM(p_s, g_hs_h);
    SYM(p_w1, g_w1t);
    SYM(p_w2, g_w2t);
    SYM(p_s1, g_s1t);
    SYM(p_s2, g_s2t);
    SYM(p_yb, g_ybuf);    SYM(p_ys, g_ys);
    SYM(p_te, g_tile_expert);

    // 1) router + bucketing
    router_kernel<<<(N + 7) / 8, 256>>>(x, rw, rb, N);
    bucket_kernel<<<1, 256>>>(N);
    // 2) operand pre-conversion
    pack_x_kernel<<<(NTOK * 512 + 255) / 256, 256>>>(x);
    pack_xg_kernel<<<(MAXP_PAD * 512 + 255) / 256, 256>>>(x);
    dim3 tb(32, 8);
    wt_kernel<<<dim3(HDIM / 32, DDIM / 64, NEXP), tb>>>(w1, (unsigned*)p_w1, DDIM, HDIM);
    wt_kernel<<<dim3(DDIM / 32, HDIM / 64, NEXP), tb>>>(w2, (unsigned*)p_w2, HDIM, DDIM);
    wt_kernel<<<dim3(HDIM / 32, DDIM / 64, NSH), tb>>>(sw1, (unsigned*)p_s1, DDIM, HDIM);
    wt_kernel<<<dim3(DDIM / 32, HDIM / 64, NSH), tb>>>(sw2, (unsigned*)p_s2, HDIM, DDIM);
    // 3) routed GEMM1: h = gelu(xg @ w1[e] + b1[e]) -> packed fp16 (A-format)
    mma_gemm2<1><<<dim3(HDIM / 128, TILES_MAX, 1), 512, SMEMSZ>>>(
        (unsigned*)p_g, 0, 512,
        (unsigned*)p_w1, b1, HDIM,
        nullptr, 0, 0, (unsigned*)p_h, 0, 1024,
        (const int*)p_te, DDIM / 64, HDIM / 128);
    // 4) routed GEMM2: y = h @ w2[e] + b2[e] -> fp32
    mma_gemm2<0><<<dim3(DDIM / 128, TILES_MAX, 1), 512, SMEMSZ>>>(
        (unsigned*)p_h, 0, 1024,
        (unsigned*)p_w2, b2, DDIM,
        (float*)p_yb, 0, DDIM, nullptr, 0, 0,
        (const int*)p_te, HDIM / 64, DDIM / 128);
    // 5) shared GEMM1: hs[s] = gelu(x @ sw1[s] + sb1[s]) -> packed fp16
    //    A (x) is the SAME for both shared experts -> a_z stride 0.
    mma_gemm2<1><<<dim3(HDIM / 128, MT_S, NSH), 512, SMEMSZ>>>(
        (unsigned*)p_x, 0, 512,
        (unsigned*)p_s1, sb1, HDIM,
        nullptr, 0, 0, (unsigned*)p_s, (long long)NTOK * 1024, 1024,
        nullptr, DDIM / 64, HDIM / 128);
    // 6) shared GEMM2: ys[s] = hs[s] @ sw2[s] + sb2[s] -> fp32
    mma_gemm2<0><<<dim3(DDIM / 128, MT_S, NSH), 512, SMEMSZ>>>(
        (unsigned*)p_s, (long long)NTOK * 1024, 1024,
        (unsigned*)p_s2, sb2, DDIM,
        (float*)p_ys, (long long)NTOK * DDIM, DDIM, nullptr, 0, 0,
        nullptr, HDIM / 64, DDIM / 128);
    // 7) combine
    combine_kernel<<<(N * (DDIM / 4) + 255) / 256, 256>>>(out, N);
}

// round 17
// speedup vs baseline: 2.1173x; 1.0039x over previous
#include <cuda_runtime.h>
#include <cuda_fp16.h>
#include <math.h>
#include <stdint.h>

// Problem constants: B=4, L=2048 -> N=8192 tokens
#define NTOK 8192
#define DDIM 1024
#define HDIM 2048
#define NEXP 8
#define NSH 2
#define MAXP (2 * NTOK)
#define MAXP_PAD (MAXP + NEXP * 128)  // 17408
#define TILES_MAX (MAXP_PAD / 128)    // 136
#define MT_S (NTOK / 128)             // 64

// GEMM staging geometry (words = 32-bit packed fp16 pairs)
// CTA tile 128(M) x 256(N), BK=64. A: 128 rows x 32 words; B: 256 rows x 32 words; stride 36.
#define NSTG 3
#define RSTRIDE 36
#define AH_OFF 0
#define BH_OFF 4608                    // 128*36
#define STG_W 13824                    // 4608 + 256*36 words per stage (54KB)
#define SMEMSZ (NSTG * STG_W * 4)      // 165888 bytes

// ------------------------- scratch (__device__ globals) -------------------------
__device__ unsigned g_x_h [(size_t)NTOK * 512];
__device__ unsigned g_xg_h[(size_t)MAXP_PAD * 512];
__device__ unsigned g_h_h [(size_t)MAXP_PAD * 1024];
__device__ unsigned g_hs_h[(size_t)NSH * NTOK * 1024];
__device__ unsigned g_w1t [(size_t)NEXP * 512 * HDIM];
__device__ unsigned g_w2t [(size_t)NEXP * 1024 * DDIM];
__device__ unsigned g_s1t [(size_t)NSH * 512 * HDIM];
__device__ unsigned g_s2t [(size_t)NSH * 1024 * DDIM];
__device__ float g_ybuf[(size_t)MAXP_PAD * DDIM];
__device__ float g_ys[(size_t)NSH * NTOK * DDIM];
__device__ int   g_pair_token[MAXP_PAD];
__device__ int   g_slot_of[MAXP];
__device__ float g_gate[MAXP];
__device__ int   g_topi[MAXP];
__device__ int   g_tile_expert[TILES_MAX];

// ------------------------- helpers -------------------------
__device__ __forceinline__ uint32_t smem_u32(const void* p) {
    uint32_t a;
    asm("{ .reg .u64 t; cvta.to.shared.u64 t, %1; cvt.u32.u64 %0, t; }" : "=r"(a) : "l"(p));
    return a;
}
__device__ __forceinline__ void cp16(uint32_t dst, const void* src) {
    asm volatile("cp.async.cg.shared.global [%0], [%1], 16;" :: "r"(dst), "l"(src) : "memory");
}
#define CP_COMMIT() asm volatile("cp.async.commit_group;" ::: "memory")
#define CP_WAIT1() asm volatile("cp.async.wait_group 1;" ::: "memory")

#define LDSM4(r0, r1, r2, r3, addr)                                           \
    asm volatile("ldmatrix.sync.aligned.m8n8.x4.shared.b16 {%0,%1,%2,%3},[%4];" \
                 : "=r"(r0), "=r"(r1), "=r"(r2), "=r"(r3) : "r"(addr))
#define LDSM2(r0, r1, addr)                                                   \
    asm volatile("ldmatrix.sync.aligned.m8n8.x2.shared.b16 {%0,%1},[%2];"     \
                 : "=r"(r0), "=r"(r1) : "r"(addr))

// fp16 pack (pair of floats -> one b32 word)
__device__ __forceinline__ unsigned cvt_one_h(float x0, float x1) {
    return (unsigned)__half_as_ushort(__float2half_rn(x0)) |
           ((unsigned)__half_as_ushort(__float2half_rn(x1)) << 16);
}

#define MMA_F16(accp, a, b)                                                   \
    asm volatile(                                                             \
        "mma.sync.aligned.m16n8k16.row.col.f32.f16.f16.f32 "                  \
        "{%0,%1,%2,%3},{%4,%5,%6,%7},{%8,%9},{%0,%1,%2,%3};"                  \
        : "+f"((accp)[0]), "+f"((accp)[1]), "+f"((accp)[2]), "+f"((accp)[3])  \
        : "r"((a)[0]), "r"((a)[1]), "r"((a)[2]), "r"((a)[3]),                 \
          "r"((b)[0]), "r"((b)[1]))

// ------------------------- router -------------------------
__global__ void router_kernel(const float* __restrict__ x, const float* __restrict__ rw,
                              const float* __restrict__ rb, int N) {
    int w = (blockIdx.x * blockDim.x + threadIdx.x) >> 5;
    int lane = threadIdx.x & 31;
    if (w >= N) return;
    const float* xr = x + (size_t)w * DDIM;
    float acc[NEXP];
#pragma unroll
    for (int e = 0; e < NEXP; e++) acc[e] = 0.f;
    for (int d = lane; d < DDIM; d += 32) {
        float xv = xr[d];
        const float* r = rw + (size_t)d * NEXP;
#pragma unroll
        for (int e = 0; e < NEXP; e++) acc[e] = fmaf(xv, r[e], acc[e]);
    }
#pragma unroll
    for (int e = 0; e < NEXP; e++)
        for (int o = 16; o > 0; o >>= 1) acc[e] += __shfl_xor_sync(0xffffffffu, acc[e], o);
    if (lane == 0) {
        float v0 = -1e30f, v1 = -1e30f;
        int i0 = 0, i1 = 0;
#pragma unroll
        for (int e = 0; e < NEXP; e++) {
            float v = acc[e] + rb[e];
            if (v > v0) { v1 = v0; i1 = i0; v0 = v; i0 = e; }
            else if (v > v1) { v1 = v; i1 = e; }
        }
        float p1 = expf(v1 - v0);
        float inv = 1.0f / (1.0f + p1);
        g_topi[2 * w] = i0; g_topi[2 * w + 1] = i1;
        g_gate[2 * w] = inv; g_gate[2 * w + 1] = p1 * inv;
    }
}

// ------------------------- bucketing -------------------------
__global__ void bucket_kernel(int N) {
    __shared__ int s_cnt[NEXP];
    __shared__ int s_off[NEXP + 1];
    __shared__ int s_c2[NEXP];
    int tid = threadIdx.x;
    if (tid < NEXP) { s_cnt[tid] = 0; s_c2[tid] = 0; }
    __syncthreads();
    int P = 2 * N;
    for (int p = tid; p < P; p += blockDim.x) atomicAdd(&s_cnt[g_topi[p]], 1);
    for (int i = tid; i < MAXP_PAD; i += blockDim.x) g_pair_token[i] = -1;
    __syncthreads();
    if (tid == 0) {
        int o = 0;
        for (int e = 0; e < NEXP; e++) { s_off[e] = o; o += ((s_cnt[e] + 127) >> 7) << 7; }
        s_off[NEXP] = o;
        int total = o >> 7;
        for (int t = 0; t < TILES_MAX; t++) {
            int ex = -1;
            if (t < total) {
                int s = t << 7;
                for (int e = 0; e < NEXP; e++)
                    if (s >= s_off[e] && s < s_off[e + 1]) ex = e;
            }
            g_tile_expert[t] = ex;
        }
    }
    __syncthreads();
    for (int p = tid; p < P; p += blockDim.x) {
        int e = g_topi[p];
        int pos = atomicAdd(&s_c2[e], 1);
        int slot = s_off[e] + pos;
        g_pair_token[slot] = p >> 1;
        g_slot_of[p] = slot;
    }
}

// ------------------------- operand pre-conversion -------------------------
// merged: x -> g_x_h, then gathered x -> g_xg_h
__global__ void pack_kernel(const float* __restrict__ x) {
    size_t idx = (size_t)blockIdx.x * blockDim.x + threadIdx.x;
    const size_t n1 = (size_t)NTOK * 512;
    const size_t n2 = n1 + (size_t)MAXP_PAD * 512;
    if (idx < n1) {
        float2 v = *(const float2*)(x + 2 * idx);
        g_x_h[idx] = cvt_one_h(v.x, v.y);
    } else if (idx < n2) {
        size_t j = idx - n1;
        int slot = (int)(j >> 9), w = (int)(j & 511);
        int tok = g_pair_token[slot];
        float2 v = (tok >= 0) ? *(const float2*)(x + (size_t)tok * DDIM + 2 * w)
                              : make_float2(0.f, 0.f);
        g_xg_h[j] = cvt_one_h(v.x, v.y);
    }
}
// W [Z][K][N] fp32 -> n-major blocks [(z*NT+nt)*KC + kc][n 256][kpair 16], single fp16
// merged: z < Za reads Wa -> oa, else Wb -> ob. NT = N/256, kc = 32-k chunks.
__global__ void wt_kernel(const float* __restrict__ Wa, int Za,
                          const float* __restrict__ Wb,
                          unsigned* __restrict__ oa, unsigned* __restrict__ ob,
                          int K, int N) {
    __shared__ float t[64][33];
    int z = blockIdx.z;
    const float* Wz;
    unsigned* oh;
    int zz;
    if (z < Za) { Wz = Wa + (size_t)z * K * N; oh = oa; zz = z; }
    else        { Wz = Wb + (size_t)(z - Za) * K * N; oh = ob; zz = z - Za; }
    int k0 = blockIdx.y * 64, n0 = blockIdx.x * 32;
    int tx = threadIdx.x, ty = threadIdx.y;
#pragma unroll
    for (int i = 0; i < 8; i++) {
        int k = ty + i * 8;
        t[k][tx] = Wz[(size_t)(k0 + k) * N + n0 + tx];
    }
    __syncthreads();
    int tid = ty * 32 + tx;
    int nl = tid >> 3, w8 = tid & 7;
    int NT = N >> 8, KC = K >> 5;
    int nabs = n0 + nl, nt = nabs >> 8, nin = nabs & 255;
#pragma unroll
    for (int kcb = 0; kcb < 2; kcb++) {
        int kc = (k0 >> 5) + kcb;
        size_t base = ((size_t)(zz * NT + nt) * KC + kc) * 4096 + (size_t)nin * 16;
#pragma unroll
        for (int j = 0; j < 2; j++) {
            int kp = w8 * 2 + j;
            int kloc = kcb * 32 + kp * 2;
            oh[base + kp] = cvt_one_h(t[kloc][nl], t[kloc + 1][nl]);
        }
    }
}

// ------------------------- merged mma.sync GEMM: 128x256 CTA, 512 threads, BK=64 -------------------------
// grid.y = TILES_MAX (routed, expert via te) + NSH*MT_S (shared, z = (y-136)>>6).
// 16 warps (4M x 4N), 32x64 C per warp, single-fp16, fp32 accum, 3-stage cp.async.
// GELU=0: C fp32 += bias. GELU=1: gelu(C+bias) -> packed fp16 words (A-format, ld = NT*128 words).
template <int GELU>
__global__ void __launch_bounds__(512, 1)
mma_gemm3(const unsigned* __restrict__ A_r,
          const unsigned* __restrict__ A_s, long long as_z,
          const unsigned* __restrict__ B_r, const unsigned* __restrict__ B_s,
          const float* __restrict__ bias_r, const float* __restrict__ bias_s,
          float* __restrict__ C_r, float* __restrict__ C_s,
          unsigned* __restrict__ O_r, unsigned* __restrict__ O_s,
          const int* __restrict__ te, int nKb, int NT) {
    int nt = blockIdx.x, mt = blockIdx.y;
    int a_ld = nKb * 32;          // words per A row (K/2)
    int ld_out = NT * 256;        // output row length (elements)

    const unsigned *Abase, *Bbase;
    const float* bias;
    unsigned* Oout = nullptr;
    float* Cout = nullptr;
    int row0;
    if (mt < TILES_MAX) {
        int e = te[mt];
        if (e < 0) return;
        Abase = A_r + (size_t)mt * 128 * a_ld;
        Bbase = B_r + (size_t)(e * NT + nt) * (size_t)nKb * 8192;
        bias = bias_r + (size_t)e * ld_out;
        if (GELU) Oout = O_r; else Cout = C_r;
        row0 = mt * 128;
    } else {
        int u = mt - TILES_MAX, z = u >> 6, mr = u & 63;
        Abase = A_s + (size_t)z * as_z + (size_t)mr * 128 * a_ld;
        Bbase = B_s + (size_t)(z * NT + nt) * (size_t)nKb * 8192;
        bias = bias_s + (size_t)z * ld_out;
        if (GELU) Oout = O_s + (size_t)z * NTOK * (ld_out / 2);
        else      Cout = C_s + (size_t)z * NTOK * ld_out;
        row0 = mr * 128;
    }
    bias += nt * 256;

    extern __shared__ unsigned smw[];
    uint32_t sb = smem_u32(smw);
    int tid = threadIdx.x, lane = tid & 31, wid = tid >> 5;
    int wm = (wid & 3) * 32, wn = (wid >> 2) * 64;

    // copy decode: A 128x32 words (2 cp16/thread), B 256x32 words (4 cp16/thread)
    int rowA = tid >> 2, ca = (tid & 3) * 2;
    int rowB = tid >> 1, cb0 = (tid & 1) * 4;

    auto issue = [&](int kb) {
        uint32_t st = sb + (uint32_t)((kb % NSTG) * STG_W) * 4;
#pragma unroll
        for (int cc = 0; cc < 2; cc++) {
            int c = ca + cc;
            cp16(st + (uint32_t)(AH_OFF + rowA * RSTRIDE + c * 4) * 4,
                 Abase + (size_t)rowA * a_ld + kb * 32 + c * 4);
        }
#pragma unroll
        for (int cc = 0; cc < 4; cc++) {
            int c = cb0 + cc;
            const unsigned* bg = Bbase + (size_t)kb * 8192 +
                                 (c < 4 ? (size_t)rowB * 16 + c * 4
                                        : 4096 + (size_t)rowB * 16 + (c - 4) * 4);
            cp16(st + (uint32_t)(BH_OFF + rowB * RSTRIDE + c * 4) * 4, bg);
        }
    };

    float acc[2][8][4];
#pragma unroll
    for (int a = 0; a < 2; a++)
#pragma unroll
        for (int b = 0; b < 8; b++)
#pragma unroll
            for (int c = 0; c < 4; c++) acc[a][b][c] = 0.f;

    // prologue: 2 stages in flight
    issue(0); CP_COMMIT();
    if (nKb > 1) issue(1);
    CP_COMMIT();

    // ldmatrix per-thread base offsets (bytes)
    uint32_t a_off = (uint32_t)((wm + (lane & 15)) * RSTRIDE + (lane >> 4) * 4) * 4;
    uint32_t b_off = (uint32_t)((wn + (lane & 7)) * RSTRIDE + ((lane >> 3) & 1) * 4) * 4;

    for (int kb = 0; kb < nKb; kb++) {
        CP_WAIT1();
        __syncthreads();
        int nx = kb + 2;
        if (nx < nKb) issue(nx);
        CP_COMMIT();

        uint32_t stg = sb + (uint32_t)((kb % NSTG) * STG_W) * 4;
        uint32_t aH = stg + AH_OFF * 4 + a_off;
        uint32_t bH = stg + BH_OFF * 4 + b_off;
#pragma unroll
        for (int ks = 0; ks < 4; ks++) {
            unsigned ah[2][4];
#pragma unroll
            for (int m2 = 0; m2 < 2; m2++) {
                uint32_t o = m2 * (16 * RSTRIDE * 4) + ks * 32;
                LDSM4(ah[m2][0], ah[m2][1], ah[m2][2], ah[m2][3], aH + o);
            }
#pragma unroll
            for (int n8 = 0; n8 < 8; n8++) {
                unsigned bh[2];
                uint32_t o = n8 * (8 * RSTRIDE * 4) + ks * 32;
                LDSM2(bh[0], bh[1], bH + o);
#pragma unroll
                for (int m2 = 0; m2 < 2; m2++) MMA_F16(acc[m2][n8], ah[m2], bh);
            }
        }
    }

    // epilogue
#pragma unroll
    for (int m2 = 0; m2 < 2; m2++) {
#pragma unroll
        for (int n8 = 0; n8 < 8; n8++) {
            int row = row0 + wm + m2 * 16 + (lane >> 2);
            int c0 = wn + n8 * 8 + (lane & 3) * 2;
            float b0 = bias[c0], b1 = bias[c0 + 1];
            float v0 = acc[m2][n8][0] + b0;
            float v1 = acc[m2][n8][1] + b1;
            float v2 = acc[m2][n8][2] + b0;
            float v3 = acc[m2][n8][3] + b1;
            if (GELU) {
                v0 = 0.5f * v0 * (1.0f + erff(v0 * 0.70710678118654752f));
                v1 = 0.5f * v1 * (1.0f + erff(v1 * 0.70710678118654752f));
                v2 = 0.5f * v2 * (1.0f + erff(v2 * 0.70710678118654752f));
                v3 = 0.5f * v3 * (1.0f + erff(v3 * 0.70710678118654752f));
                int ldw = ld_out >> 1;
                size_t w = (size_t)((nt * 256 + c0) >> 1);
                size_t b0i = (size_t)row * ldw + w;
                size_t b1i = b0i + (size_t)8 * ldw;
                Oout[b0i] = cvt_one_h(v0, v1);
                Oout[b1i] = cvt_one_h(v2, v3);
            } else {
                size_t base = (size_t)row * ld_out + nt * 256 + c0;
                *(float2*)&Cout[base] = make_float2(v0, v1);
                *(float2*)&Cout[base + (size_t)8 * ld_out] = make_float2(v2, v3);
            }
        }
    }
}

// ------------------------- final combine -------------------------
__global__ void combine_kernel(float* __restrict__ out, int N) {
    int idx = blockIdx.x * blockDim.x + threadIdx.x;
    int total = N * (DDIM / 4);
    if (idx >= total) return;
    int n = idx / (DDIM / 4);
    int d = (idx % (DDIM / 4)) * 4;
    const float4 s0 = *(const float4*)&g_ys[(size_t)n * DDIM + d];
    const float4 s1 = *(const float4*)&g_ys[(size_t)N * DDIM + (size_t)n * DDIM + d];
    int sl0 = g_slot_of[2 * n], sl1 = g_slot_of[2 * n + 1];
    float w0 = g_gate[2 * n], w1 = g_gate[2 * n + 1];
    const float4 y0 = *(const float4*)&g_ybuf[(size_t)sl0 * DDIM + d];
    const float4 y1 = *(const float4*)&g_ybuf[(size_t)sl1 * DDIM + d];
    const float inv_s = 1.0f / NSH;
    float4 o;
    o.x = inv_s * (s0.x + s1.x) + w0 * y0.x + w1 * y1.x;
    o.y = inv_s * (s0.y + s1.y) + w0 * y0.y + w1 * y1.y;
    o.z = inv_s * (s0.z + s1.z) + w0 * y0.z + w1 * y1.z;
    o.w = inv_s * (s0.w + s1.w) + w0 * y0.w + w1 * y1.w;
    *(float4*)&out[(size_t)n * DDIM + d] = o;
}

// ------------------------- launch -------------------------
#define SYM(p, s) void* p; cudaGetSymbolAddress(&p, s)

extern "C" void kernel_launch(void* const* d_in, const int* in_sizes, int n_in,
                              void* d_out, int out_size) {
    const float* x   = (const float*)d_in[0];
    const float* rw  = (const float*)d_in[1];
    const float* rb  = (const float*)d_in[2];
    const float* w1  = (const float*)d_in[3];
    const float* b1  = (const float*)d_in[4];
    const float* w2  = (const float*)d_in[5];
    const float* b2  = (const float*)d_in[6];
    const float* sw1 = (const float*)d_in[7];
    const float* sb1 = (const float*)d_in[8];
    const float* sw2 = (const float*)d_in[9];
    const float* sb2 = (const float*)d_in[10];
    float* out = (float*)d_out;
    int N = in_sizes[0] / DDIM;

    cudaFuncSetAttribute(mma_gemm3<0>, cudaFuncAttributeMaxDynamicSharedMemorySize, SMEMSZ);
    cudaFuncSetAttribute(mma_gemm3<1>, cudaFuncAttributeMaxDynamicSharedMemorySize, SMEMSZ);

    SYM(p_x, g_x_h);
    SYM(p_g, g_xg_h);
    SYM(p_h, g_h_h);
    SYM(p_s, g_hs_h);
    SYM(p_w1, g_w1t);
    SYM(p_w2, g_w2t);
    SYM(p_s1, g_s1t);
    SYM(p_s2, g_s2t);
    SYM(p_yb, g_ybuf);    SYM(p_ys, g_ys);
    SYM(p_te, g_tile_expert);

    // 1) router + bucketing
    router_kernel<<<(N + 7) / 8, 256>>>(x, rw, rb, N);
    bucket_kernel<<<1, 256>>>(N);
    // 2) operand pre-conversion (merged)
    {
        size_t tot = (size_t)NTOK * 512 + (size_t)MAXP_PAD * 512;
        pack_kernel<<<(int)((tot + 255) / 256), 256>>>(x);
    }
    dim3 tb(32, 8);
    wt_kernel<<<dim3(HDIM / 32, DDIM / 64, NEXP + NSH), tb>>>(
        w1, NEXP, sw1, (unsigned*)p_w1, (unsigned*)p_s1, DDIM, HDIM);
    wt_kernel<<<dim3(DDIM / 32, HDIM / 64, NEXP + NSH), tb>>>(
        w2, NEXP, sw2, (unsigned*)p_w2, (unsigned*)p_s2, HDIM, DDIM);
    // 3) merged GEMM1: routed h = gelu(xg@w1[e]+b1[e]) AND shared hs[s] = gelu(x@sw1[s]+sb1[s])
    mma_gemm3<1><<<dim3(HDIM / 256, TILES_MAX + NSH * MT_S, 1), 512, SMEMSZ>>>(
        (unsigned*)p_g, (unsigned*)p_x, 0,
        (unsigned*)p_w1, (unsigned*)p_s1, b1, sb1,
        nullptr, nullptr, (unsigned*)p_h, (unsigned*)p_s,
        (const int*)p_te, DDIM / 64, HDIM / 256);
    // 4) merged GEMM2: routed y = h@w2[e]+b2[e] AND shared ys[s] = hs[s]@sw2[s]+sb2[s]
    mma_gemm3<0><<<dim3(DDIM / 256, TILES_MAX + NSH * MT_S, 1), 512, SMEMSZ>>>(
        (unsigned*)p_h, (unsigned*)p_s, (long long)NTOK * 1024,
        (unsigned*)p_w2, (unsigned*)p_s2, b2, sb2,
        (float*)p_yb, (float*)p_ys, nullptr, nullptr,
        (const int*)p_te, HDIM / 64, DDIM / 256);
    // 5) combine
    combine_kernel<<<(N * (DDIM / 4) + 255) / 256, 256>>>(out, N);
}